// round 13
// baseline (speedup 1.0000x reference)
#include <cuda_runtime.h>
#include <cstdint>
#include <math.h>

#define S_LEN 768
#define EMB   128
#define HDIM  256
#define G4    1024
#define MLPD  128
#define CLUST 16

// ---------------- scratch (static device memory; no allocation) ----------------
__device__ float d_x  [S_LEN * EMB];
__device__ float d_gxF[S_LEN * G4];
__device__ float d_gxB[S_LEN * G4];
__device__ float d_h0 [S_LEN * 2 * HDIM];
__device__ float d_h1 [S_LEN * 2 * HDIM];
__device__ float d_hA [S_LEN * MLPD];
__device__ float d_hB [S_LEN * MLPD];

// ---------------- fast activations ----------------
__device__ __forceinline__ float sigmoidf_fast(float x) {
    return __fdividef(1.f, 1.f + __expf(-x));
}
__device__ __forceinline__ float tanhf_fast(float x) {
    float e = __expf(-2.f * fabsf(x));
    float r = __fdividef(1.f - e, 1.f + e);
    return copysignf(r, x);
}

// ---------------- cluster / mbarrier helpers ----------------
__device__ __forceinline__ uint32_t smem_u32(const void* p) {
    uint32_t a;
    asm("{ .reg .u64 t; cvta.to.shared.u64 t, %1; cvt.u32.u64 %0, t; }"
        : "=r"(a) : "l"(p));
    return a;
}
__device__ __forceinline__ uint32_t mapa_u32(uint32_t local_addr, uint32_t rank) {
    uint32_t rem;
    asm volatile("mapa.shared::cluster.u32 %0, %1, %2;"
                 : "=r"(rem) : "r"(local_addr), "r"(rank));
    return rem;
}
// bulk DSMEM copy with tx-completion at the (remote) destination mbarrier
__device__ __forceinline__ void bulk_copy_cluster(uint32_t dst_cluster, uint32_t src_cta,
                                                  uint32_t bytes, uint32_t bar_cluster) {
    asm volatile(
        "cp.async.bulk.shared::cluster.shared::cta.mbarrier::complete_tx::bytes "
        "[%0], [%1], %2, [%3];"
        :: "r"(dst_cluster), "r"(src_cta), "r"(bytes), "r"(bar_cluster) : "memory");
}
__device__ __forceinline__ void fence_proxy_async_cta() {
    asm volatile("fence.proxy.async.shared::cta;" ::: "memory");
}
__device__ __forceinline__ void arrive_expect_tx(uint32_t bar, uint32_t bytes) {
    asm volatile("mbarrier.arrive.expect_tx.shared.b64 _, [%0], %1;"
                 :: "r"(bar), "r"(bytes) : "memory");
}
// two-phase wait: fast try, then sleep-loop with timeout hint (parked wait —
// measured equal-best; parking frees the SMSP for the OTHER direction's warps)
__device__ __forceinline__ void wait_parity(uint32_t bar, uint32_t parity) {
    uint32_t done;
    asm volatile(
        "{\n\t"
        ".reg .pred P;\n\t"
        "mbarrier.try_wait.parity.acquire.cta.shared::cta.b64 P, [%1], %2;\n\t"
        "selp.b32 %0, 1, 0, P;\n\t"
        "}"
        : "=r"(done) : "r"(bar), "r"(parity) : "memory");
    if (!done) {
        asm volatile(
            "{\n\t"
            ".reg .pred P;\n\t"
            "W%=:\n\t"
            "mbarrier.try_wait.parity.acquire.cta.shared::cta.b64 P, [%0], %1, 0x989680;\n\t"
            "@!P bra W%=;\n\t"
            "}"
            :: "r"(bar), "r"(parity) : "memory");
    }
}
__device__ __forceinline__ void cluster_sync_() {
    asm volatile("barrier.cluster.arrive.aligned;" ::: "memory");
    asm volatile("barrier.cluster.wait.aligned;" ::: "memory");
}
__device__ __forceinline__ uint32_t cluster_rank_() {
    uint32_t r; asm("mov.u32 %0, %%cluster_ctarank;" : "=r"(r)); return r;
}

#define FMA2(acc, w, h) \
    asm("fma.rn.f32x2 %0, %1, %2, %0;" : "+l"(acc) : "l"(w), "l"(h))

// ---------------- embedding gather ----------------
__global__ void embed_kernel(const int* __restrict__ widx, const int* __restrict__ pidx,
                             const float* __restrict__ Ww, const float* __restrict__ Wp) {
    int s = blockIdx.x, f = threadIdx.x;
    float v = (f < 100) ? Ww[widx[s] * 100 + f] : Wp[pidx[s] * 28 + (f - 100)];
    d_x[s * EMB + f] = v;
}

// ---------------- generic C[M,N] = A[M,K] * B[N,K]^T + bias1 + bias2 ----------------
__global__ __launch_bounds__(256) void gemm_bias_kernel(
    const float* __restrict__ A, int lda,
    const float* __restrict__ B, int ldb,
    const float* __restrict__ bias1, const float* __restrict__ bias2,
    float* __restrict__ C, int ldc,
    int M, int N, int K)
{
    __shared__ __align__(16) float As[16][68];
    __shared__ __align__(16) float Bs[16][68];
    int tid = threadIdx.x;
    int bx = blockIdx.x, by = blockIdx.y;
    int tx = tid & 15, ty = tid >> 4;
    int m0 = by * 64 + ty * 4;
    int n0 = bx * 64 + tx * 4;
    float acc[4][4] = {};

    for (int k0 = 0; k0 < K; k0 += 16) {
#pragma unroll
        for (int i = 0; i < 4; i++) {
            int idx = tid + i * 256;
            int r = idx >> 4, kk = idx & 15;
            int col = k0 + kk;
            int mrow = by * 64 + r;
            int nrow = bx * 64 + r;
            As[kk][r] = (mrow < M && col < K) ? A[mrow * lda + col] : 0.f;
            Bs[kk][r] = (nrow < N && col < K) ? B[nrow * ldb + col] : 0.f;
        }
        __syncthreads();
#pragma unroll
        for (int kk = 0; kk < 16; kk++) {
            float4 av = *reinterpret_cast<const float4*>(&As[kk][ty * 4]);
            float4 bv = *reinterpret_cast<const float4*>(&Bs[kk][tx * 4]);
            float a[4] = {av.x, av.y, av.z, av.w};
            float b[4] = {bv.x, bv.y, bv.z, bv.w};
#pragma unroll
            for (int i = 0; i < 4; i++)
#pragma unroll
                for (int j = 0; j < 4; j++)
                    acc[i][j] = fmaf(a[i], b[j], acc[i][j]);
        }
        __syncthreads();
    }
#pragma unroll
    for (int i = 0; i < 4; i++)
#pragma unroll
        for (int j = 0; j < 4; j++) {
            int r = m0 + i, c = n0 + j;
            if (r < M && c < N) {
                float bv = 0.f;
                if (bias1) bv += bias1[c];
                if (bias2) bv += bias2[c];
                C[r * ldc + c] = acc[i][j] + bv;
            }
        }
}

// ---------------- BiLSTM recurrence: ONE 16-CTA cluster, BOTH directions ----------------
// Latency hiding by co-scheduling: each CTA hosts two independent 128-thread
// groups (fwd = threads 0..127, bwd = 128..255), each a complete R4-style
// recurrence unit over 16 hidden units:
//   - hf-split dot (64 FMA2/thread over register-resident fp32 weights)
//   - group-named bar.sync(1+d), warp0-of-group activation tail
//   - ping-pong stage; 16 x 64B cp.async.bulk with tx at each peer's per-dir
//     ping-pong mbarrier (expect_tx = 16*64 = 1024B); parked try_wait.
// When group F's warps park on their mbarrier, group B's warps issue — the
// exchange latency of one direction hides behind the other's compute.
__global__ void __cluster_dims__(CLUST, 1, 1) __launch_bounds__(256, 1)
lstm_kernel(const float* __restrict__ WhhF, const float* __restrict__ WhhB,
            const float* __restrict__ gxF,  const float* __restrict__ gxB,
            float* __restrict__ hout)
{
    __shared__ __align__(16) float hbuf[2][2][256];        // [dir][parity][256]
    __shared__ __align__(16) float stage[2][2][16];        // [dir][parity][16 units]
    __shared__ float gates[2][64];                         // [dir][gate*16+unit]
    __shared__ __align__(8) unsigned long long mbar[2][2]; // [dir][parity]

    int tid   = threadIdx.x;
    uint32_t crank = cluster_rank_();
    int d     = tid >> 7;                 // 0 = fwd group, 1 = bwd group
    int gtid  = tid & 127;                // thread id within group
    const float* Whh = d ? WhhB : WhhF;
    const float* gx  = d ? gxB  : gxF;

    int rl   = gtid >> 1;                 // gate row 0..63 within CTA slice
    int hf   = gtid & 1;                  // half of the 256 h values
    int gate = rl >> 4, unit = rl & 15;   // gates[d][gate*16+unit]
    int grow = gate * 256 + (int)crank * 16 + unit;

    // register-resident weights, packed f32x2 (128 floats per thread)
    unsigned long long w2[64];
    const ulonglong2* wsrc = reinterpret_cast<const ulonglong2*>(Whh + grow * 256 + hf * 128);
#pragma unroll
    for (int k = 0; k < 32; k++) {
        ulonglong2 v = wsrc[k];
        w2[2 * k] = v.x; w2[2 * k + 1] = v.y;
    }

    for (int i = tid; i < 2 * 2 * 256; i += 256) (&hbuf[0][0][0])[i] = 0.f;
    if (tid == 0) {
        uint32_t b0 = smem_u32(&mbar[0][0]);
#pragma unroll
        for (int i = 0; i < 4; i++)
            asm volatile("mbarrier.init.shared.b64 [%0], 1;" :: "r"(b0 + 8u * i) : "memory");
    }
    __syncthreads();
    cluster_sync_();   // bars initialized + h zeroed cluster-wide before any tx

    uint32_t hbase  = smem_u32(&hbuf[d][0][0]);
    uint32_t stbase = smem_u32(&stage[d][0][0]);
    uint32_t barb   = smem_u32(&mbar[d][0]);

    // sender mapping (warp0 of group; lanes 0..15 send, peer = lane)
    int lane = gtid & 31;
    uint32_t peer  = (uint32_t)(lane & 15);
    uint32_t mych  = (uint32_t)crank * 64u;
    uint32_t dstP0 = mapa_u32(hbase + mych,          peer);  // peer hbuf[d][0] slice
    uint32_t dstP1 = mapa_u32(hbase + 1024u + mych,  peer);  // peer hbuf[d][1] slice
    uint32_t rb0   = mapa_u32(barb,      peer);              // peer bar[d][0]
    uint32_t rb1   = mapa_u32(barb + 8u, peer);              // peer bar[d][1]

    float cstate = 0.f;

    // prefetch first gx
    int s0 = d ? (S_LEN - 1) : 0;
    float gxv = gx[s0 * G4 + grow];

    for (int t = 0; t < S_LEN; t++) {
        int s = d ? (S_LEN - 1 - t) : t;

        // re-arm this group's bar for event t (early peer tx legally goes
        // negative-pending); bar[t&1]'s previous event t-2 was consumed at
        // our step t-1 wait.
        if (gtid == 0)
            arrive_expect_tx(barb + ((uint32_t)t & 1u) * 8u, 1024u);

        // wait event t-1 (h(t) fully delivered into hbuf[d][t&1]); parked —
        // frees the SMSP for the other direction's warps
        if (t > 0) {
            uint32_t e = (uint32_t)(t - 1);
            wait_parity(barb + (e & 1u) * 8u, (e >> 1) & 1u);
        }

        // prefetch next step's gx while we compute
        float gxn = 0.f;
        if (t + 1 < S_LEN) {
            int sn = d ? (S_LEN - 2 - t) : (t + 1);
            gxn = gx[sn * G4 + grow];
        }

        // 128-wide half-row dot product, packed f32x2, 4 accumulator chains
        const ulonglong2* hv = reinterpret_cast<const ulonglong2*>(&hbuf[d][t & 1][hf * 128]);
        unsigned long long a0 = 0ull, a1 = 0ull, a2 = 0ull, a3 = 0ull;
#pragma unroll
        for (int k = 0; k < 32; k += 2) {
            ulonglong2 hA2 = hv[k];
            ulonglong2 hB2 = hv[k + 1];
            FMA2(a0, w2[2 * k],     hA2.x);
            FMA2(a1, w2[2 * k + 1], hA2.y);
            FMA2(a2, w2[2 * k + 2], hB2.x);
            FMA2(a3, w2[2 * k + 3], hB2.y);
        }
        float f0, f1, f2, f3, f4, f5, f6, f7;
        asm("mov.b64 {%0, %1}, %2;" : "=f"(f0), "=f"(f1) : "l"(a0));
        asm("mov.b64 {%0, %1}, %2;" : "=f"(f2), "=f"(f3) : "l"(a1));
        asm("mov.b64 {%0, %1}, %2;" : "=f"(f4), "=f"(f5) : "l"(a2));
        asm("mov.b64 {%0, %1}, %2;" : "=f"(f6), "=f"(f7) : "l"(a3));
        float dot = ((f0 + f1) + (f2 + f3)) + ((f4 + f5) + (f6 + f7));
        dot += __shfl_xor_sync(0xffffffffu, dot, 1);
        if (hf == 0) gates[d][rl] = gxv + dot;
        // group barrier (named, 128 threads)
        if (d == 0) asm volatile("bar.sync 1, 128;" ::: "memory");
        else        asm volatile("bar.sync 2, 128;" ::: "memory");

        if (gtid < 32) {
            float hn = 0.f;
            if (lane < 16) {
                int u = lane;
                float gi = sigmoidf_fast(gates[d][u]);
                float gf = sigmoidf_fast(gates[d][16 + u]);
                float gg = tanhf_fast   (gates[d][32 + u]);
                float go = sigmoidf_fast(gates[d][48 + u]);
                cstate   = gf * cstate + gi * gg;
                hn = go * tanhf_fast(cstate);
                stage[d][(t + 1) & 1][u] = hn;
            }
            __syncwarp();
            fence_proxy_async_cta();   // stage -> async proxy
            if (lane < 16) {
                uint32_t src = stbase + (uint32_t)(((t + 1) & 1) * 64);
                uint32_t dd  = (t & 1) ? dstP0 : dstP1;   // write hbuf[d][(t+1)&1]
                uint32_t bb  = (t & 1) ? rb1   : rb0;     // account at bar[d][t&1]
                bulk_copy_cluster(dd, src, 64u, bb);
                hout[s * 512 + d * 256 + (int)crank * 16 + lane] = hn;
            }
        }
        gxv = gxn;
    }

    // drain this group's final event so no copy is in flight at teardown
    {
        uint32_t e = (uint32_t)(S_LEN - 1);
        wait_parity(barb + (e & 1u) * 8u, (e >> 1) & 1u);
    }
    cluster_sync_();
}

// ---------------- pairwise scorer ----------------
__global__ __launch_bounds__(256) void scorer_kernel(
    const float* __restrict__ hA, const float* __restrict__ hB,
    const float* __restrict__ W2, const float* __restrict__ b2,
    float* __restrict__ out)
{
    __shared__ float sA[16][129];
    __shared__ float sB[16][129];
    __shared__ float sw[128];
    int tid = threadIdx.x;
    int j0 = blockIdx.x * 16, i0 = blockIdx.y * 16;

    for (int idx = tid; idx < 16 * 128; idx += 256) {
        int r = idx >> 7, k = idx & 127;
        sA[r][k] = hA[(i0 + r) * MLPD + k];
        sB[r][k] = hB[(j0 + r) * MLPD + k];
    }
    if (tid < 128) sw[tid] = W2[tid];
    __syncthreads();

    int tx = tid & 15, ty = tid >> 4;
    float acc = b2[0];
#pragma unroll 4
    for (int k = 0; k < 128; k++) {
        float v = sA[ty][k] + sB[tx][k];
        acc = fmaf(sw[k], tanhf_fast(v), acc);
    }
    int i = i0 + ty, j = j0 + tx;
    out[i * S_LEN + j] = (i == j) ? 0.f : acc;
}

// ---------------- launch ----------------
extern "C" void kernel_launch(void* const* d_in, const int* in_sizes, int n_in,
                              void* d_out, int out_size)
{
    int base = (in_sizes[2] < 1000) ? 3 : 2;

    const int* widx = (const int*)d_in[0];
    const int* pidx = (const int*)d_in[1];
    const float* W_word = (const float*)d_in[base + 0];
    const float* W_pos  = (const float*)d_in[base + 1];
    const float *Wih[4], *Whh[4], *bih[4], *bhh[4];
    for (int i = 0; i < 4; i++) {
        Wih[i] = (const float*)d_in[base + 2 + 4 * i];
        Whh[i] = (const float*)d_in[base + 3 + 4 * i];
        bih[i] = (const float*)d_in[base + 4 + 4 * i];
        bhh[i] = (const float*)d_in[base + 5 + 4 * i];
    }
    const float* W1 = (const float*)d_in[base + 18];
    const float* b1 = (const float*)d_in[base + 19];
    const float* W2 = (const float*)d_in[base + 20];
    const float* b2 = (const float*)d_in[base + 21];
    float* out = (float*)d_out;

    float *xp, *gxF, *gxB, *h0, *h1, *hA, *hB;
    cudaGetSymbolAddress((void**)&xp,  d_x);
    cudaGetSymbolAddress((void**)&gxF, d_gxF);
    cudaGetSymbolAddress((void**)&gxB, d_gxB);
    cudaGetSymbolAddress((void**)&h0,  d_h0);
    cudaGetSymbolAddress((void**)&h1,  d_h1);
    cudaGetSymbolAddress((void**)&hA,  d_hA);
    cudaGetSymbolAddress((void**)&hB,  d_hB);

    // allow nonportable cluster size 16 (host-side attribute, not a stream op)
    cudaFuncSetAttribute((const void*)lstm_kernel,
                         cudaFuncAttributeNonPortableClusterSizeAllowed, 1);

    // 1) embeddings
    embed_kernel<<<S_LEN, EMB>>>(widx, pidx, W_word, W_pos);

    // 2) layer-0 input GEMMs: gx = x @ Wih^T + bih + bhh   [768,1024]
    dim3 gGX(G4 / 64, S_LEN / 64);
    gemm_bias_kernel<<<gGX, 256>>>(xp, EMB, Wih[0], EMB, bih[0], bhh[0], gxF, G4, S_LEN, G4, EMB);
    gemm_bias_kernel<<<gGX, 256>>>(xp, EMB, Wih[1], EMB, bih[1], bhh[1], gxB, G4, S_LEN, G4, EMB);

    // 3) layer-0 recurrence (both directions in ONE 16-CTA cluster)
    lstm_kernel<<<CLUST, 256>>>(Whh[0], Whh[1], gxF, gxB, h0);

    // 4) layer-1 input GEMMs: gx = h0 @ Wih^T + biases  (K = 512)
    gemm_bias_kernel<<<gGX, 256>>>(h0, 512, Wih[2], 512, bih[2], bhh[2], gxF, G4, S_LEN, G4, 512);
    gemm_bias_kernel<<<gGX, 256>>>(h0, 512, Wih[3], 512, bih[3], bhh[3], gxB, G4, S_LEN, G4, 512);

    // 5) layer-1 recurrence
    lstm_kernel<<<CLUST, 256>>>(Whh[2], Whh[3], gxF, gxB, h1);

    // 6) scorer projections
    dim3 gAB(MLPD / 64, S_LEN / 64);
    gemm_bias_kernel<<<gAB, 256>>>(h1, 512, W1,       1024, b1,      nullptr, hA, MLPD, S_LEN, MLPD, 512);
    gemm_bias_kernel<<<gAB, 256>>>(h1, 512, W1 + 512, 1024, nullptr, nullptr, hB, MLPD, S_LEN, MLPD, 512);

    // 7) pairwise scores [768,768], diag = 0
    scorer_kernel<<<dim3(S_LEN / 16, S_LEN / 16), 256>>>(hA, hB, W2, b2, out);
}

// round 14
// speedup vs baseline: 1.0807x; 1.0807x over previous
#include <cuda_runtime.h>
#include <cstdint>
#include <math.h>

#define S_LEN 768
#define EMB   128
#define HDIM  256
#define G4    1024
#define MLPD  128
#define NTHR  288   // 8 compute warps + 1 comm warp

// ---------------- scratch (static device memory; no allocation) ----------------
__device__ float d_x  [S_LEN * EMB];
__device__ float d_gxF[S_LEN * G4];
__device__ float d_gxB[S_LEN * G4];
__device__ float d_h0 [S_LEN * 2 * HDIM];
__device__ float d_h1 [S_LEN * 2 * HDIM];
__device__ float d_hA [S_LEN * MLPD];
__device__ float d_hB [S_LEN * MLPD];

// ---------------- fast activations ----------------
__device__ __forceinline__ float sigmoidf_fast(float x) {
    return __fdividef(1.f, 1.f + __expf(-x));
}
__device__ __forceinline__ float tanhf_fast(float x) {
    float e = __expf(-2.f * fabsf(x));
    float r = __fdividef(1.f - e, 1.f + e);
    return copysignf(r, x);
}

// ---------------- cluster / mbarrier helpers ----------------
__device__ __forceinline__ uint32_t smem_u32(const void* p) {
    uint32_t a;
    asm("{ .reg .u64 t; cvta.to.shared.u64 t, %1; cvt.u32.u64 %0, t; }"
        : "=r"(a) : "l"(p));
    return a;
}
__device__ __forceinline__ uint32_t mapa_u32(uint32_t local_addr, uint32_t rank) {
    uint32_t rem;
    asm volatile("mapa.shared::cluster.u32 %0, %1, %2;"
                 : "=r"(rem) : "r"(local_addr), "r"(rank));
    return rem;
}
// bulk DSMEM copy with tx-completion at the (remote) destination mbarrier
__device__ __forceinline__ void bulk_copy_cluster(uint32_t dst_cluster, uint32_t src_cta,
                                                  uint32_t bytes, uint32_t bar_cluster) {
    asm volatile(
        "cp.async.bulk.shared::cluster.shared::cta.mbarrier::complete_tx::bytes "
        "[%0], [%1], %2, [%3];"
        :: "r"(dst_cluster), "r"(src_cta), "r"(bytes), "r"(bar_cluster) : "memory");
}
__device__ __forceinline__ void fence_proxy_async_cta() {
    asm volatile("fence.proxy.async.shared::cta;" ::: "memory");
}
__device__ __forceinline__ void arrive_expect_tx(uint32_t bar, uint32_t bytes) {
    asm volatile("mbarrier.arrive.expect_tx.shared.b64 _, [%0], %1;"
                 :: "r"(bar), "r"(bytes) : "memory");
}
// two-phase wait: fast try, then sleep-loop with timeout hint (parked wait —
// measured equal-best; nothing else competes for the SM so parking is free)
__device__ __forceinline__ void wait_parity(uint32_t bar, uint32_t parity) {
    uint32_t done;
    asm volatile(
        "{\n\t"
        ".reg .pred P;\n\t"
        "mbarrier.try_wait.parity.acquire.cta.shared::cta.b64 P, [%1], %2;\n\t"
        "selp.b32 %0, 1, 0, P;\n\t"
        "}"
        : "=r"(done) : "r"(bar), "r"(parity) : "memory");
    if (!done) {
        asm volatile(
            "{\n\t"
            ".reg .pred P;\n\t"
            "W%=:\n\t"
            "mbarrier.try_wait.parity.acquire.cta.shared::cta.b64 P, [%0], %1, 0x989680;\n\t"
            "@!P bra W%=;\n\t"
            "}"
            :: "r"(bar), "r"(parity) : "memory");
    }
}
__device__ __forceinline__ void cluster_sync_() {
    asm volatile("barrier.cluster.arrive.aligned;" ::: "memory");
    asm volatile("barrier.cluster.wait.aligned;" ::: "memory");
}
__device__ __forceinline__ uint32_t cluster_rank_() {
    uint32_t r; asm("mov.u32 %0, %%cluster_ctarank;" : "=r"(r)); return r;
}

#define FMA2(acc, w, h) \
    asm("fma.rn.f32x2 %0, %1, %2, %0;" : "+l"(acc) : "l"(w), "l"(h))

// ---------------- embedding gather ----------------
__global__ void embed_kernel(const int* __restrict__ widx, const int* __restrict__ pidx,
                             const float* __restrict__ Ww, const float* __restrict__ Wp) {
    int s = blockIdx.x, f = threadIdx.x;
    float v = (f < 100) ? Ww[widx[s] * 100 + f] : Wp[pidx[s] * 28 + (f - 100)];
    d_x[s * EMB + f] = v;
}

// ---------------- generic C[M,N] = A[M,K] * B[N,K]^T + bias1 + bias2 ----------------
__global__ __launch_bounds__(256) void gemm_bias_kernel(
    const float* __restrict__ A, int lda,
    const float* __restrict__ B, int ldb,
    const float* __restrict__ bias1, const float* __restrict__ bias2,
    float* __restrict__ C, int ldc,
    int M, int N, int K)
{
    __shared__ __align__(16) float As[16][68];
    __shared__ __align__(16) float Bs[16][68];
    int tid = threadIdx.x;
    int bx = blockIdx.x, by = blockIdx.y;
    int tx = tid & 15, ty = tid >> 4;
    int m0 = by * 64 + ty * 4;
    int n0 = bx * 64 + tx * 4;
    float acc[4][4] = {};

    for (int k0 = 0; k0 < K; k0 += 16) {
#pragma unroll
        for (int i = 0; i < 4; i++) {
            int idx = tid + i * 256;
            int r = idx >> 4, kk = idx & 15;
            int col = k0 + kk;
            int mrow = by * 64 + r;
            int nrow = bx * 64 + r;
            As[kk][r] = (mrow < M && col < K) ? A[mrow * lda + col] : 0.f;
            Bs[kk][r] = (nrow < N && col < K) ? B[nrow * ldb + col] : 0.f;
        }
        __syncthreads();
#pragma unroll
        for (int kk = 0; kk < 16; kk++) {
            float4 av = *reinterpret_cast<const float4*>(&As[kk][ty * 4]);
            float4 bv = *reinterpret_cast<const float4*>(&Bs[kk][tx * 4]);
            float a[4] = {av.x, av.y, av.z, av.w};
            float b[4] = {bv.x, bv.y, bv.z, bv.w};
#pragma unroll
            for (int i = 0; i < 4; i++)
#pragma unroll
                for (int j = 0; j < 4; j++)
                    acc[i][j] = fmaf(a[i], b[j], acc[i][j]);
        }
        __syncthreads();
    }
#pragma unroll
    for (int i = 0; i < 4; i++)
#pragma unroll
        for (int j = 0; j < 4; j++) {
            int r = m0 + i, c = n0 + j;
            if (r < M && c < N) {
                float bv = 0.f;
                if (bias1) bv += bias1[c];
                if (bias2) bv += bias2[c];
                C[r * ldc + c] = acc[i][j] + bv;
            }
        }
}

// ---------------- BiLSTM recurrence: 2 clusters x 8 CTAs x 288 threads ----------------
// R14 = R7 champion minus two serial links:
//   - compute warps (0..7): wait the ping-pong mbarrier DIRECTLY (parked
//     try_wait — R4-measured equal-best), dot over register-resident weights,
//     shfl-assembled gates (R6 layout, no syncthreads), STS 4 h values into
//     the parity stage, bar.arrive(1), loop. NO release barrier, NO fence,
//     NO sends on the compute path.
//   - comm warp (8): PURE sender. bar.sync(1) collects (drains STS), ONE
//     fence.proxy.async.shared::cta, lanes 0..7 issue ONE 128B cp.async.bulk
//     each to one peer's hbuf slot, tx-accounted at that peer's bar[t&1]
//     (8 tx + 1 arrive per bar per step). Never touches the local mbarrier.
//   - tid0 arms event t (expect_tx 1024B) at its step-t top; early peer tx is
//     legal (tx-count negative-pending).
//   - the last step's copy (event S-1, h(S): never consumed) is skipped, so
//     teardown needs no drain: the last in-flight copies (event S-2) completed
//     before computes passed their final wait.
__global__ void __cluster_dims__(8, 1, 1) __launch_bounds__(NTHR, 1)
lstm_kernel(const float* __restrict__ WhhF, const float* __restrict__ WhhB,
            const float* __restrict__ gxF,  const float* __restrict__ gxB,
            float* __restrict__ hout)
{
    __shared__ __align__(16) float hbuf[2][256];          // ping-pong full h vector
    __shared__ __align__(16) float stage[2][32];          // ping-pong outgoing slice
    __shared__ __align__(8) unsigned long long mbar[2];   // ping-pong (bar[t&1])

    int tid   = threadIdx.x;
    uint32_t crank = cluster_rank_();
    int dir   = blockIdx.x >> 3;           // 0 = fwd, 1 = bwd
    const float* gx  = dir ? gxB  : gxF;

    int lane = tid & 31, w = tid >> 5;

    if (tid == 0) {
        uint32_t b0 = smem_u32(&mbar[0]);
        asm volatile("mbarrier.init.shared.b64 [%0], 1;" :: "r"(b0) : "memory");
        asm volatile("mbarrier.init.shared.b64 [%0], 1;" :: "r"(b0 + 8) : "memory");
    }
    for (int i = tid; i < 512; i += NTHR) (&hbuf[0][0])[i] = 0.f;

    uint32_t hbase   = smem_u32(&hbuf[0][0]);
    uint32_t stbase  = smem_u32(&stage[0][0]);
    uint32_t barbase = smem_u32(&mbar[0]);

    if (w == 8) {
        // ---------------- comm warp: pure sender ----------------
        __syncthreads();
        cluster_sync_();   // bars initialized + h zeroed everywhere

        uint32_t peer  = (uint32_t)(lane & 7);
        uint32_t mych  = (uint32_t)crank * 128u;
        uint32_t dstP0 = mapa_u32(hbase + mych,         peer);  // into peer hbuf[0]
        uint32_t dstP1 = mapa_u32(hbase + 1024u + mych, peer);  // into peer hbuf[1]
        uint32_t rb0   = mapa_u32(barbase,      peer);          // peer bar[0]
        uint32_t rb1   = mapa_u32(barbase + 8u, peer);          // peer bar[1]

        for (int t = 0; t < S_LEN; t++) {
            // collect: computes staged h(t+1) during their step t
            asm volatile("bar.sync 1, %0;" :: "n"(NTHR) : "memory");
            if (t < S_LEN - 1) {     // event S-1 (h(S)) is never consumed: skip
                fence_proxy_async_cta();   // computes' STS -> async proxy
                if (lane < 8) {
                    uint32_t src = stbase + (uint32_t)(((t + 1) & 1) * 128);
                    uint32_t d   = (t & 1) ? dstP0 : dstP1;   // write peer hbuf[(t+1)&1]
                    uint32_t b   = (t & 1) ? rb1   : rb0;     // account at peer bar[t&1]
                    bulk_copy_cluster(d, src, 128u, b);
                }
            }
        }
        cluster_sync_();
    } else {
        // ---------------- compute warps (0..7) ----------------
        const float* Whh = dir ? WhhB : WhhF;

        int gate = lane >> 3;                  // 0=i 1=f 2=g 3=o
        int ul   = (lane >> 1) & 3;            // unit within warp
        int hf   = lane & 1;                   // which half of h
        int unit = w * 4 + ul;                 // unit within CTA (0..31)
        int grow = gate * 256 + (int)crank * 32 + unit;

        // register-resident weights, packed f32x2 (128 floats per lane)
        unsigned long long w2[64];
        const ulonglong2* wsrc = reinterpret_cast<const ulonglong2*>(Whh + grow * 256 + hf * 128);
#pragma unroll
        for (int k = 0; k < 32; k++) {
            ulonglong2 v = wsrc[k];
            w2[2 * k] = v.x; w2[2 * k + 1] = v.y;
        }

        __syncthreads();
        cluster_sync_();

        float cstate = 0.f;

        // prefetch first gx
        int s0 = dir ? (S_LEN - 1) : 0;
        float gxv = gx[s0 * G4 + grow];

        for (int t = 0; t < S_LEN; t++) {
            int s = dir ? (S_LEN - 1 - t) : t;

            // arm event t: 8 peers x 128B into hbuf[(t+1)&1], counted at bar[t&1]
            if (tid == 0)
                arrive_expect_tx(barbase + ((uint32_t)t & 1u) * 8u, 1024u);

            // wait event t-1 directly (h(t) fully delivered into hbuf[t&1]);
            // parked wait, no fan-out barrier
            if (t > 0) {
                uint32_t e = (uint32_t)(t - 1);
                wait_parity(barbase + (e & 1u) * 8u, (e >> 1) & 1u);
            }

            // prefetch next step's gx while we compute
            float gxn = 0.f;
            if (t + 1 < S_LEN) {
                int sn = dir ? (S_LEN - 2 - t) : (t + 1);
                gxn = gx[sn * G4 + grow];
            }

            // 128-wide dot product, packed f32x2, 4 accumulator chains
            const ulonglong2* hv = reinterpret_cast<const ulonglong2*>(&hbuf[t & 1][hf * 128]);
            unsigned long long a0 = 0ull, a1 = 0ull, a2 = 0ull, a3 = 0ull;
#pragma unroll
            for (int k = 0; k < 32; k += 2) {
                ulonglong2 hA2 = hv[k];
                ulonglong2 hB2 = hv[k + 1];
                FMA2(a0, w2[2 * k],     hA2.x);
                FMA2(a1, w2[2 * k + 1], hA2.y);
                FMA2(a2, w2[2 * k + 2], hB2.x);
                FMA2(a3, w2[2 * k + 3], hB2.y);
            }
            float f0, f1, f2, f3, f4, f5, f6, f7;
            asm("mov.b64 {%0, %1}, %2;" : "=f"(f0), "=f"(f1) : "l"(a0));
            asm("mov.b64 {%0, %1}, %2;" : "=f"(f2), "=f"(f3) : "l"(a1));
            asm("mov.b64 {%0, %1}, %2;" : "=f"(f4), "=f"(f5) : "l"(a2));
            asm("mov.b64 {%0, %1}, %2;" : "=f"(f6), "=f"(f7) : "l"(a3));
            float dot = ((f0 + f1) + (f2 + f3)) + ((f4 + f5) + (f6 + f7));
            dot += __shfl_xor_sync(0xffffffffu, dot, 1);

            // gate pre-activation, unified activation (tanh(v) = 2*sigmoid(2v)-1)
            float v = gxv + dot;
            float z   = (gate == 2) ? 2.f * v : v;
            float sg  = sigmoidf_fast(z);
            float act = (gate == 2) ? fmaf(2.f, sg, -1.f) : sg;

            // gather f, g, o to the i-gate lanes of each unit
            int srcb = lane & 7;
            float gf = __shfl_sync(0xffffffffu, act, srcb + 8);
            float gg = __shfl_sync(0xffffffffu, act, srcb + 16);
            float go = __shfl_sync(0xffffffffu, act, srcb + 24);

            cstate = fmaf(gf, cstate, act * gg);
            float hn = go * tanhf_fast(cstate);

            // stage this warp's 4 h values (same parity as target hbuf)
            if (gate == 0 && hf == 0)
                stage[(t + 1) & 1][unit] = hn;

            // hand off to the comm warp (non-blocking)
            asm volatile("bar.arrive 1, %0;" :: "n"(NTHR) : "memory");

            // off critical path: write h to global
            if (gate == 0 && hf == 0)
                hout[s * 512 + dir * 256 + (int)crank * 32 + unit] = hn;

            gxv = gxn;
        }
        cluster_sync_();
    }
}

// ---------------- pairwise scorer ----------------
__global__ __launch_bounds__(256) void scorer_kernel(
    const float* __restrict__ hA, const float* __restrict__ hB,
    const float* __restrict__ W2, const float* __restrict__ b2,
    float* __restrict__ out)
{
    __shared__ float sA[16][129];
    __shared__ float sB[16][129];
    __shared__ float sw[128];
    int tid = threadIdx.x;
    int j0 = blockIdx.x * 16, i0 = blockIdx.y * 16;

    for (int idx = tid; idx < 16 * 128; idx += 256) {
        int r = idx >> 7, k = idx & 127;
        sA[r][k] = hA[(i0 + r) * MLPD + k];
        sB[r][k] = hB[(j0 + r) * MLPD + k];
    }
    if (tid < 128) sw[tid] = W2[tid];
    __syncthreads();

    int tx = tid & 15, ty = tid >> 4;
    float acc = b2[0];
#pragma unroll 4
    for (int k = 0; k < 128; k++) {
        float v = sA[ty][k] + sB[tx][k];
        acc = fmaf(sw[k], tanhf_fast(v), acc);
    }
    int i = i0 + ty, j = j0 + tx;
    out[i * S_LEN + j] = (i == j) ? 0.f : acc;
}

// ---------------- launch ----------------
extern "C" void kernel_launch(void* const* d_in, const int* in_sizes, int n_in,
                              void* d_out, int out_size)
{
    int base = (in_sizes[2] < 1000) ? 3 : 2;

    const int* widx = (const int*)d_in[0];
    const int* pidx = (const int*)d_in[1];
    const float* W_word = (const float*)d_in[base + 0];
    const float* W_pos  = (const float*)d_in[base + 1];
    const float *Wih[4], *Whh[4], *bih[4], *bhh[4];
    for (int i = 0; i < 4; i++) {
        Wih[i] = (const float*)d_in[base + 2 + 4 * i];
        Whh[i] = (const float*)d_in[base + 3 + 4 * i];
        bih[i] = (const float*)d_in[base + 4 + 4 * i];
        bhh[i] = (const float*)d_in[base + 5 + 4 * i];
    }
    const float* W1 = (const float*)d_in[base + 18];
    const float* b1 = (const float*)d_in[base + 19];
    const float* W2 = (const float*)d_in[base + 20];
    const float* b2 = (const float*)d_in[base + 21];
    float* out = (float*)d_out;

    float *xp, *gxF, *gxB, *h0, *h1, *hA, *hB;
    cudaGetSymbolAddress((void**)&xp,  d_x);
    cudaGetSymbolAddress((void**)&gxF, d_gxF);
    cudaGetSymbolAddress((void**)&gxB, d_gxB);
    cudaGetSymbolAddress((void**)&h0,  d_h0);
    cudaGetSymbolAddress((void**)&h1,  d_h1);
    cudaGetSymbolAddress((void**)&hA,  d_hA);
    cudaGetSymbolAddress((void**)&hB,  d_hB);

    // 1) embeddings
    embed_kernel<<<S_LEN, EMB>>>(widx, pidx, W_word, W_pos);

    // 2) layer-0 input GEMMs: gx = x @ Wih^T + bih + bhh   [768,1024]
    dim3 gGX(G4 / 64, S_LEN / 64);
    gemm_bias_kernel<<<gGX, 256>>>(xp, EMB, Wih[0], EMB, bih[0], bhh[0], gxF, G4, S_LEN, G4, EMB);
    gemm_bias_kernel<<<gGX, 256>>>(xp, EMB, Wih[1], EMB, bih[1], bhh[1], gxB, G4, S_LEN, G4, EMB);

    // 3) layer-0 recurrence (fwd + bwd concurrently)
    lstm_kernel<<<16, NTHR>>>(Whh[0], Whh[1], gxF, gxB, h0);

    // 4) layer-1 input GEMMs: gx = h0 @ Wih^T + biases  (K = 512)
    gemm_bias_kernel<<<gGX, 256>>>(h0, 512, Wih[2], 512, bih[2], bhh[2], gxF, G4, S_LEN, G4, 512);
    gemm_bias_kernel<<<gGX, 256>>>(h0, 512, Wih[3], 512, bih[3], bhh[3], gxB, G4, S_LEN, G4, 512);

    // 5) layer-1 recurrence
    lstm_kernel<<<16, NTHR>>>(Whh[2], Whh[3], gxF, gxB, h1);

    // 6) scorer projections
    dim3 gAB(MLPD / 64, S_LEN / 64);
    gemm_bias_kernel<<<gAB, 256>>>(h1, 512, W1,       1024, b1,      nullptr, hA, MLPD, S_LEN, MLPD, 512);
    gemm_bias_kernel<<<gAB, 256>>>(h1, 512, W1 + 512, 1024, nullptr, nullptr, hB, MLPD, S_LEN, MLPD, 512);

    // 7) pairwise scores [768,768], diag = 0
    scorer_kernel<<<dim3(S_LEN / 16, S_LEN / 16), 256>>>(hA, hB, W2, b2, out);
}

// round 15
// speedup vs baseline: 1.3109x; 1.2130x over previous
#include <cuda_runtime.h>
#include <cstdint>
#include <math.h>

#define S_LEN 768
#define EMB   128
#define HDIM  256
#define G4    1024
#define MLPD  128

// ---------------- scratch (static device memory; no allocation) ----------------
__device__ float d_x  [S_LEN * EMB];
__device__ float d_gxF[S_LEN * G4];
__device__ float d_gxB[S_LEN * G4];
__device__ float d_h0 [S_LEN * 2 * HDIM];
__device__ float d_h1 [S_LEN * 2 * HDIM];
__device__ float d_hA [S_LEN * MLPD];
__device__ float d_hB [S_LEN * MLPD];

// ---------------- fast activations ----------------
// single-MUFU tanh (sm_75+); sigma(x) = 0.5 + 0.5*tanh(x/2) = MUFU.TANH + FFMA
__device__ __forceinline__ float tanh_mufu(float x) {
    float r; asm("tanh.approx.f32 %0, %1;" : "=f"(r) : "f"(x)); return r;
}
__device__ __forceinline__ float tanhf_fast(float x) {   // scorer path (accuracy-cheap)
    return tanh_mufu(x);
}

// ---------------- cluster / mbarrier helpers ----------------
__device__ __forceinline__ uint32_t smem_u32(const void* p) {
    uint32_t a;
    asm("{ .reg .u64 t; cvta.to.shared.u64 t, %1; cvt.u32.u64 %0, t; }"
        : "=r"(a) : "l"(p));
    return a;
}
__device__ __forceinline__ uint32_t mapa_u32(uint32_t local_addr, uint32_t rank) {
    uint32_t rem;
    asm volatile("mapa.shared::cluster.u32 %0, %1, %2;"
                 : "=r"(rem) : "r"(local_addr), "r"(rank));
    return rem;
}
// bulk DSMEM copy with tx-completion at the (remote) destination mbarrier
__device__ __forceinline__ void bulk_copy_cluster(uint32_t dst_cluster, uint32_t src_cta,
                                                  uint32_t bytes, uint32_t bar_cluster) {
    asm volatile(
        "cp.async.bulk.shared::cluster.shared::cta.mbarrier::complete_tx::bytes "
        "[%0], [%1], %2, [%3];"
        :: "r"(dst_cluster), "r"(src_cta), "r"(bytes), "r"(bar_cluster) : "memory");
}
__device__ __forceinline__ void fence_proxy_async_cta() {
    asm volatile("fence.proxy.async.shared::cta;" ::: "memory");
}
__device__ __forceinline__ void arrive_expect_tx(uint32_t bar, uint32_t bytes) {
    asm volatile("mbarrier.arrive.expect_tx.shared.b64 _, [%0], %1;"
                 :: "r"(bar), "r"(bytes) : "memory");
}
// two-phase wait: fast try, then sleep-loop with timeout hint (parked wait)
__device__ __forceinline__ void wait_parity(uint32_t bar, uint32_t parity) {
    uint32_t done;
    asm volatile(
        "{\n\t"
        ".reg .pred P;\n\t"
        "mbarrier.try_wait.parity.acquire.cta.shared::cta.b64 P, [%1], %2;\n\t"
        "selp.b32 %0, 1, 0, P;\n\t"
        "}"
        : "=r"(done) : "r"(bar), "r"(parity) : "memory");
    if (!done) {
        asm volatile(
            "{\n\t"
            ".reg .pred P;\n\t"
            "W%=:\n\t"
            "mbarrier.try_wait.parity.acquire.cta.shared::cta.b64 P, [%0], %1, 0x989680;\n\t"
            "@!P bra W%=;\n\t"
            "}"
            :: "r"(bar), "r"(parity) : "memory");
    }
}
__device__ __forceinline__ void cluster_sync_() {
    asm volatile("barrier.cluster.arrive.aligned;" ::: "memory");
    asm volatile("barrier.cluster.wait.aligned;" ::: "memory");
}
__device__ __forceinline__ uint32_t cluster_rank_() {
    uint32_t r; asm("mov.u32 %0, %%cluster_ctarank;" : "=r"(r)); return r;
}

#define FMA2(acc, w, h) \
    asm("fma.rn.f32x2 %0, %1, %2, %0;" : "+l"(acc) : "l"(w), "l"(h))

// ---------------- embedding gather ----------------
__global__ void embed_kernel(const int* __restrict__ widx, const int* __restrict__ pidx,
                             const float* __restrict__ Ww, const float* __restrict__ Wp) {
    int s = blockIdx.x, f = threadIdx.x;
    float v = (f < 100) ? Ww[widx[s] * 100 + f] : Wp[pidx[s] * 28 + (f - 100)];
    d_x[s * EMB + f] = v;
}

// ---------------- generic C[M,N] = A[M,K] * B[N,K]^T + bias1 + bias2 ----------------
__global__ __launch_bounds__(256) void gemm_bias_kernel(
    const float* __restrict__ A, int lda,
    const float* __restrict__ B, int ldb,
    const float* __restrict__ bias1, const float* __restrict__ bias2,
    float* __restrict__ C, int ldc,
    int M, int N, int K)
{
    __shared__ __align__(16) float As[16][68];
    __shared__ __align__(16) float Bs[16][68];
    int tid = threadIdx.x;
    int bx = blockIdx.x, by = blockIdx.y;
    int tx = tid & 15, ty = tid >> 4;
    int m0 = by * 64 + ty * 4;
    int n0 = bx * 64 + tx * 4;
    float acc[4][4] = {};

    for (int k0 = 0; k0 < K; k0 += 16) {
#pragma unroll
        for (int i = 0; i < 4; i++) {
            int idx = tid + i * 256;
            int r = idx >> 4, kk = idx & 15;
            int col = k0 + kk;
            int mrow = by * 64 + r;
            int nrow = bx * 64 + r;
            As[kk][r] = (mrow < M && col < K) ? A[mrow * lda + col] : 0.f;
            Bs[kk][r] = (nrow < N && col < K) ? B[nrow * ldb + col] : 0.f;
        }
        __syncthreads();
#pragma unroll
        for (int kk = 0; kk < 16; kk++) {
            float4 av = *reinterpret_cast<const float4*>(&As[kk][ty * 4]);
            float4 bv = *reinterpret_cast<const float4*>(&Bs[kk][tx * 4]);
            float a[4] = {av.x, av.y, av.z, av.w};
            float b[4] = {bv.x, bv.y, bv.z, bv.w};
#pragma unroll
            for (int i = 0; i < 4; i++)
#pragma unroll
                for (int j = 0; j < 4; j++)
                    acc[i][j] = fmaf(a[i], b[j], acc[i][j]);
        }
        __syncthreads();
    }
#pragma unroll
    for (int i = 0; i < 4; i++)
#pragma unroll
        for (int j = 0; j < 4; j++) {
            int r = m0 + i, c = n0 + j;
            if (r < M && c < N) {
                float bv = 0.f;
                if (bias1) bv += bias1[c];
                if (bias2) bv += bias2[c];
                C[r * ldc + c] = acc[i][j] + bv;
            }
        }
}

// ---------------- BiLSTM recurrence: 2 clusters x 8 CTAs x 256 threads ----------------
// R6 champion-class structure with three compute-side trims:
//   1. MUFU.TANH activations: tanh = 1 MUFU op; sigma(x)=0.5+0.5*tanh(x/2)
//      (cuts the serial gate tail by ~half).
//   2. gx prefetch issued BEFORE the parked wait (LDG in flight during park).
//   3. the last step's send (event S-1, h(S): never consumed) is skipped, and
//      the teardown drain with it — after the final wait(S-2) nothing is in
//      flight that touches smem.
// Exchange mechanics identical to R6: distributed gates (no syncthreads),
// warp7 collects via bar.sync(1), one fence.proxy.async, 8 x 128B bulk
// copies tx-accounted at each peer's ping-pong bar; tid0 arms expect_tx(1024)
// at step top (early tx legally negative-pending); parked try_wait.
__global__ void __cluster_dims__(8, 1, 1) __launch_bounds__(256, 1)
lstm_kernel(const float* __restrict__ WhhF, const float* __restrict__ WhhB,
            const float* __restrict__ gxF,  const float* __restrict__ gxB,
            float* __restrict__ hout)
{
    __shared__ __align__(16) float hbuf[2][256];          // ping-pong full h vector
    __shared__ __align__(16) float stage[2][32];          // ping-pong outgoing slice
    __shared__ __align__(8) unsigned long long mbar[2];   // ping-pong (bar[t&1])

    int tid   = threadIdx.x;
    uint32_t crank = cluster_rank_();
    int dir   = blockIdx.x >> 3;           // 0 = fwd, 1 = bwd
    const float* Whh = dir ? WhhB : WhhF;
    const float* gx  = dir ? gxB  : gxF;

    int lane = tid & 31, w = tid >> 5;
    int gate = lane >> 3;                  // 0=i 1=f 2=g 3=o
    int ul   = (lane >> 1) & 3;            // unit within warp
    int hf   = lane & 1;                   // which half of h
    int unit = w * 4 + ul;                 // unit within CTA (0..31)
    int grow = gate * 256 + (int)crank * 32 + unit;

    // register-resident weights, packed f32x2 (128 floats per lane)
    unsigned long long w2[64];
    const ulonglong2* wsrc = reinterpret_cast<const ulonglong2*>(Whh + grow * 256 + hf * 128);
#pragma unroll
    for (int k = 0; k < 32; k++) {
        ulonglong2 v = wsrc[k];
        w2[2 * k] = v.x; w2[2 * k + 1] = v.y;
    }

    for (int i = tid; i < 512; i += 256) (&hbuf[0][0])[i] = 0.f;
    if (tid == 0) {
        uint32_t b0 = smem_u32(&mbar[0]);
        asm volatile("mbarrier.init.shared.b64 [%0], 1;" :: "r"(b0) : "memory");
        asm volatile("mbarrier.init.shared.b64 [%0], 1;" :: "r"(b0 + 8) : "memory");
    }
    __syncthreads();
    cluster_sync_();   // bars initialized + h zeroed before anyone copies/arrives

    uint32_t hbase   = smem_u32(&hbuf[0][0]);
    uint32_t stbase  = smem_u32(&stage[0][0]);
    uint32_t barbase = smem_u32(&mbar[0]);

    // sender mapping (warp7, lanes 0..7: peer = lane)
    uint32_t peer  = (uint32_t)(lane & 7);
    uint32_t mych  = (uint32_t)crank * 128u;
    uint32_t dstP0 = mapa_u32(hbase + mych,          peer);  // into peer hbuf[0]
    uint32_t dstP1 = mapa_u32(hbase + 1024u + mych,  peer);  // into peer hbuf[1]
    uint32_t rb0   = mapa_u32(barbase,      peer);           // peer bar[0]
    uint32_t rb1   = mapa_u32(barbase + 8u, peer);           // peer bar[1]

    float cstate = 0.f;

    // prefetch first gx
    int s0 = dir ? (S_LEN - 1) : 0;
    float gxv = gx[s0 * G4 + grow];

    for (int t = 0; t < S_LEN; t++) {
        int s = dir ? (S_LEN - 1 - t) : t;

        // arm event t: 8 peers x 128B into hbuf[(t+1)&1], counted at bar[t&1]
        if (tid == 0)
            arrive_expect_tx(barbase + ((uint32_t)t & 1u) * 8u, 1024u);

        // prefetch next step's gx BEFORE parking (LDG flies during the wait)
        float gxn = 0.f;
        if (t + 1 < S_LEN) {
            int sn = dir ? (S_LEN - 2 - t) : (t + 1);
            gxn = gx[sn * G4 + grow];
        }

        // wait event t-1 (h(t) fully delivered into hbuf[t&1]); parked
        if (t > 0) {
            uint32_t e = (uint32_t)(t - 1);
            wait_parity(barbase + (e & 1u) * 8u, (e >> 1) & 1u);
        }

        // 128-wide dot product, packed f32x2, 4 accumulator chains
        const ulonglong2* hv = reinterpret_cast<const ulonglong2*>(&hbuf[t & 1][hf * 128]);
        unsigned long long a0 = 0ull, a1 = 0ull, a2 = 0ull, a3 = 0ull;
#pragma unroll
        for (int k = 0; k < 32; k += 2) {
            ulonglong2 hA2 = hv[k];
            ulonglong2 hB2 = hv[k + 1];
            FMA2(a0, w2[2 * k],     hA2.x);
            FMA2(a1, w2[2 * k + 1], hA2.y);
            FMA2(a2, w2[2 * k + 2], hB2.x);
            FMA2(a3, w2[2 * k + 3], hB2.y);
        }
        float f0, f1, f2, f3, f4, f5, f6, f7;
        asm("mov.b64 {%0, %1}, %2;" : "=f"(f0), "=f"(f1) : "l"(a0));
        asm("mov.b64 {%0, %1}, %2;" : "=f"(f2), "=f"(f3) : "l"(a1));
        asm("mov.b64 {%0, %1}, %2;" : "=f"(f4), "=f"(f5) : "l"(a2));
        asm("mov.b64 {%0, %1}, %2;" : "=f"(f6), "=f"(f7) : "l"(a3));
        float dot = ((f0 + f1) + (f2 + f3)) + ((f4 + f5) + (f6 + f7));
        dot += __shfl_xor_sync(0xffffffffu, dot, 1);

        // gate activation via single-MUFU tanh:
        //   g gate (gate==2): act = tanh(v)
        //   i/f/o gates:      act = 0.5 + 0.5*tanh(v/2)
        float v  = gxv + dot;
        float z  = (gate == 2) ? v : 0.5f * v;
        float th = tanh_mufu(z);
        float act = (gate == 2) ? th : fmaf(0.5f, th, 0.5f);

        // gather f, g, o to the i-gate lanes of each unit
        int srcb = lane & 7;
        float gf = __shfl_sync(0xffffffffu, act, srcb + 8);
        float gg = __shfl_sync(0xffffffffu, act, srcb + 16);
        float go = __shfl_sync(0xffffffffu, act, srcb + 24);

        cstate = fmaf(gf, cstate, act * gg);
        float hn = go * tanh_mufu(cstate);

        // stage this warp's 4 h values (same parity as target hbuf)
        if (gate == 0 && hf == 0)
            stage[(t + 1) & 1][unit] = hn;

        if (w != 7) {
            asm volatile("bar.arrive 1, 256;" ::: "memory");
        } else {
            asm volatile("bar.sync 1, 256;" ::: "memory");   // drains all warps' STS
            if (t < S_LEN - 1) {          // event S-1 (h(S)) is never consumed: skip
                fence_proxy_async_cta();  // make stage async-visible
                if (lane < 8) {
                    uint32_t src = stbase + (uint32_t)(((t + 1) & 1) * 128);
                    uint32_t d   = (t & 1) ? dstP0 : dstP1;   // write hbuf[(t+1)&1]
                    uint32_t b   = (t & 1) ? rb1   : rb0;     // account at bar[t&1]
                    bulk_copy_cluster(d, src, 128u, b);
                }
            }
        }

        // off critical path: write h to global
        if (gate == 0 && hf == 0)
            hout[s * 512 + dir * 256 + (int)crank * 32 + unit] = hn;

        gxv = gxn;
    }
    // no drain needed: the last copies (event S-2) completed before every CTA
    // passed its final wait; event S-1 was never sent.
    cluster_sync_();
}

// ---------------- pairwise scorer ----------------
__global__ __launch_bounds__(256) void scorer_kernel(
    const float* __restrict__ hA, const float* __restrict__ hB,
    const float* __restrict__ W2, const float* __restrict__ b2,
    float* __restrict__ out)
{
    __shared__ float sA[16][129];
    __shared__ float sB[16][129];
    __shared__ float sw[128];
    int tid = threadIdx.x;
    int j0 = blockIdx.x * 16, i0 = blockIdx.y * 16;

    for (int idx = tid; idx < 16 * 128; idx += 256) {
        int r = idx >> 7, k = idx & 127;
        sA[r][k] = hA[(i0 + r) * MLPD + k];
        sB[r][k] = hB[(j0 + r) * MLPD + k];
    }
    if (tid < 128) sw[tid] = W2[tid];
    __syncthreads();

    int tx = tid & 15, ty = tid >> 4;
    float acc = b2[0];
#pragma unroll 4
    for (int k = 0; k < 128; k++) {
        float v = sA[ty][k] + sB[tx][k];
        acc = fmaf(sw[k], tanhf_fast(v), acc);
    }
    int i = i0 + ty, j = j0 + tx;
    out[i * S_LEN + j] = (i == j) ? 0.f : acc;
}

// ---------------- launch ----------------
extern "C" void kernel_launch(void* const* d_in, const int* in_sizes, int n_in,
                              void* d_out, int out_size)
{
    int base = (in_sizes[2] < 1000) ? 3 : 2;

    const int* widx = (const int*)d_in[0];
    const int* pidx = (const int*)d_in[1];
    const float* W_word = (const float*)d_in[base + 0];
    const float* W_pos  = (const float*)d_in[base + 1];
    const float *Wih[4], *Whh[4], *bih[4], *bhh[4];
    for (int i = 0; i < 4; i++) {
        Wih[i] = (const float*)d_in[base + 2 + 4 * i];
        Whh[i] = (const float*)d_in[base + 3 + 4 * i];
        bih[i] = (const float*)d_in[base + 4 + 4 * i];
        bhh[i] = (const float*)d_in[base + 5 + 4 * i];
    }
    const float* W1 = (const float*)d_in[base + 18];
    const float* b1 = (const float*)d_in[base + 19];
    const float* W2 = (const float*)d_in[base + 20];
    const float* b2 = (const float*)d_in[base + 21];
    float* out = (float*)d_out;

    float *xp, *gxF, *gxB, *h0, *h1, *hA, *hB;
    cudaGetSymbolAddress((void**)&xp,  d_x);
    cudaGetSymbolAddress((void**)&gxF, d_gxF);
    cudaGetSymbolAddress((void**)&gxB, d_gxB);
    cudaGetSymbolAddress((void**)&h0,  d_h0);
    cudaGetSymbolAddress((void**)&h1,  d_h1);
    cudaGetSymbolAddress((void**)&hA,  d_hA);
    cudaGetSymbolAddress((void**)&hB,  d_hB);

    // 1) embeddings
    embed_kernel<<<S_LEN, EMB>>>(widx, pidx, W_word, W_pos);

    // 2) layer-0 input GEMMs: gx = x @ Wih^T + bih + bhh   [768,1024]
    dim3 gGX(G4 / 64, S_LEN / 64);
    gemm_bias_kernel<<<gGX, 256>>>(xp, EMB, Wih[0], EMB, bih[0], bhh[0], gxF, G4, S_LEN, G4, EMB);
    gemm_bias_kernel<<<gGX, 256>>>(xp, EMB, Wih[1], EMB, bih[1], bhh[1], gxB, G4, S_LEN, G4, EMB);

    // 3) layer-0 recurrence (fwd + bwd concurrently)
    lstm_kernel<<<16, 256>>>(Whh[0], Whh[1], gxF, gxB, h0);

    // 4) layer-1 input GEMMs: gx = h0 @ Wih^T + biases  (K = 512)
    gemm_bias_kernel<<<gGX, 256>>>(h0, 512, Wih[2], 512, bih[2], bhh[2], gxF, G4, S_LEN, G4, 512);
    gemm_bias_kernel<<<gGX, 256>>>(h0, 512, Wih[3], 512, bih[3], bhh[3], gxB, G4, S_LEN, G4, 512);

    // 5) layer-1 recurrence
    lstm_kernel<<<16, 256>>>(Whh[2], Whh[3], gxF, gxB, h1);

    // 6) scorer projections
    dim3 gAB(MLPD / 64, S_LEN / 64);
    gemm_bias_kernel<<<gAB, 256>>>(h1, 512, W1,       1024, b1,      nullptr, hA, MLPD, S_LEN, MLPD, 512);
    gemm_bias_kernel<<<gAB, 256>>>(h1, 512, W1 + 512, 1024, nullptr, nullptr, hB, MLPD, S_LEN, MLPD, 512);

    // 7) pairwise scores [768,768], diag = 0
    scorer_kernel<<<dim3(S_LEN / 16, S_LEN / 16), 256>>>(hA, hB, W2, b2, out);
}

// round 16
// speedup vs baseline: 1.3725x; 1.0470x over previous
#include <cuda_runtime.h>
#include <cstdint>
#include <math.h>

#define S_LEN 768
#define EMB   128
#define HDIM  256
#define G4    1024
#define MLPD  128

// ---------------- scratch (static device memory; no allocation) ----------------
__device__ float d_x  [S_LEN * EMB];
__device__ float d_gxF[S_LEN * G4];
__device__ float d_gxB[S_LEN * G4];
__device__ float d_h0 [S_LEN * 2 * HDIM];
__device__ float d_h1 [S_LEN * 2 * HDIM];
__device__ float d_hA [S_LEN * MLPD];
__device__ float d_hB [S_LEN * MLPD];

// ---------------- fast activations ----------------
__device__ __forceinline__ float tanh_mufu(float x) {
    float r; asm("tanh.approx.f32 %0, %1;" : "=f"(r) : "f"(x)); return r;
}

// ---------------- cluster / mbarrier helpers ----------------
__device__ __forceinline__ uint32_t smem_u32(const void* p) {
    uint32_t a;
    asm("{ .reg .u64 t; cvta.to.shared.u64 t, %1; cvt.u32.u64 %0, t; }"
        : "=r"(a) : "l"(p));
    return a;
}
__device__ __forceinline__ uint32_t mapa_u32(uint32_t local_addr, uint32_t rank) {
    uint32_t rem;
    asm volatile("mapa.shared::cluster.u32 %0, %1, %2;"
                 : "=r"(rem) : "r"(local_addr), "r"(rank));
    return rem;
}
__device__ __forceinline__ void bulk_copy_cluster(uint32_t dst_cluster, uint32_t src_cta,
                                                  uint32_t bytes, uint32_t bar_cluster) {
    asm volatile(
        "cp.async.bulk.shared::cluster.shared::cta.mbarrier::complete_tx::bytes "
        "[%0], [%1], %2, [%3];"
        :: "r"(dst_cluster), "r"(src_cta), "r"(bytes), "r"(bar_cluster) : "memory");
}
__device__ __forceinline__ void fence_proxy_async_cta() {
    asm volatile("fence.proxy.async.shared::cta;" ::: "memory");
}
__device__ __forceinline__ void arrive_expect_tx(uint32_t bar, uint32_t bytes) {
    asm volatile("mbarrier.arrive.expect_tx.shared.b64 _, [%0], %1;"
                 :: "r"(bar), "r"(bytes) : "memory");
}
__device__ __forceinline__ void wait_parity(uint32_t bar, uint32_t parity) {
    uint32_t done;
    asm volatile(
        "{\n\t"
        ".reg .pred P;\n\t"
        "mbarrier.try_wait.parity.acquire.cta.shared::cta.b64 P, [%1], %2;\n\t"
        "selp.b32 %0, 1, 0, P;\n\t"
        "}"
        : "=r"(done) : "r"(bar), "r"(parity) : "memory");
    if (!done) {
        asm volatile(
            "{\n\t"
            ".reg .pred P;\n\t"
            "W%=:\n\t"
            "mbarrier.try_wait.parity.acquire.cta.shared::cta.b64 P, [%0], %1, 0x989680;\n\t"
            "@!P bra W%=;\n\t"
            "}"
            :: "r"(bar), "r"(parity) : "memory");
    }
}
__device__ __forceinline__ void cluster_sync_() {
    asm volatile("barrier.cluster.arrive.aligned;" ::: "memory");
    asm volatile("barrier.cluster.wait.aligned;" ::: "memory");
}
__device__ __forceinline__ uint32_t cluster_rank_() {
    uint32_t r; asm("mov.u32 %0, %%cluster_ctarank;" : "=r"(r)); return r;
}

#define FMA2(acc, w, h) \
    asm("fma.rn.f32x2 %0, %1, %2, %0;" : "+l"(acc) : "l"(w), "l"(h))
#define PACK2(out, lo, hi) \
    asm("mov.b64 %0, {%1, %2};" : "=l"(out) : "f"(lo), "f"(hi))
#define UNPACK2(lo, hi, in) \
    asm("mov.b64 {%0, %1}, %2;" : "=f"(lo), "=f"(hi) : "l"(in))

// ---------------- embedding gather ----------------
__global__ void embed_kernel(const int* __restrict__ widx, const int* __restrict__ pidx,
                             const float* __restrict__ Ww, const float* __restrict__ Wp) {
    int s = blockIdx.x, f = threadIdx.x;
    float v = (f < 100) ? Ww[widx[s] * 100 + f] : Wp[pidx[s] * 28 + (f - 100)];
    d_x[s * EMB + f] = v;
}

// ---------------- batched pair GEMM: z selects (B, biases, C) ----------------
// C[M,N] = A[M,K] * B[N,K]^T + bias1 + bias2, inner loop in packed f32x2
// (scalar 3-reg FFMA is HALF-RATE on sm_103a; FMA2 restores full fp32 rate).
__global__ __launch_bounds__(256) void gemm_pair_kernel(
    const float* __restrict__ A, int lda,
    const float* __restrict__ B0, const float* __restrict__ B1, int ldb,
    const float* __restrict__ b1a, const float* __restrict__ b1b,
    const float* __restrict__ b2a, const float* __restrict__ b2b,
    float* __restrict__ C0, float* __restrict__ C1, int ldc,
    int M, int N, int K)
{
    int z = blockIdx.z;
    const float* B     = z ? B1  : B0;
    const float* bias1 = z ? b1b : b1a;
    const float* bias2 = z ? b2b : b2a;
    float* C           = z ? C1  : C0;

    __shared__ __align__(16) float As[16][68];
    __shared__ __align__(16) float Bs[16][68];
    int tid = threadIdx.x;
    int bx = blockIdx.x, by = blockIdx.y;
    int tx = tid & 15, ty = tid >> 4;
    int m0 = by * 64 + ty * 4;
    int n0 = bx * 64 + tx * 4;

    unsigned long long acc2[4][2];
#pragma unroll
    for (int i = 0; i < 4; i++) { acc2[i][0] = 0ull; acc2[i][1] = 0ull; }

    for (int k0 = 0; k0 < K; k0 += 16) {
#pragma unroll
        for (int i = 0; i < 4; i++) {
            int idx = tid + i * 256;
            int r = idx >> 4, kk = idx & 15;
            int col = k0 + kk;
            int mrow = by * 64 + r;
            int nrow = bx * 64 + r;
            As[kk][r] = (mrow < M && col < K) ? A[mrow * lda + col] : 0.f;
            Bs[kk][r] = (nrow < N && col < K) ? B[nrow * ldb + col] : 0.f;
        }
        __syncthreads();
#pragma unroll
        for (int kk = 0; kk < 16; kk++) {
            float4 av = *reinterpret_cast<const float4*>(&As[kk][ty * 4]);
            float4 bv = *reinterpret_cast<const float4*>(&Bs[kk][tx * 4]);
            unsigned long long b01, b23;
            PACK2(b01, bv.x, bv.y);
            PACK2(b23, bv.z, bv.w);
            float a[4] = {av.x, av.y, av.z, av.w};
#pragma unroll
            for (int i = 0; i < 4; i++) {
                unsigned long long a2;
                PACK2(a2, a[i], a[i]);
                FMA2(acc2[i][0], a2, b01);
                FMA2(acc2[i][1], a2, b23);
            }
        }
        __syncthreads();
    }
#pragma unroll
    for (int i = 0; i < 4; i++) {
        float c0, c1, c2, c3;
        UNPACK2(c0, c1, acc2[i][0]);
        UNPACK2(c2, c3, acc2[i][1]);
        float cr[4] = {c0, c1, c2, c3};
#pragma unroll
        for (int j = 0; j < 4; j++) {
            int r = m0 + i, c = n0 + j;
            if (r < M && c < N) {
                float bv = 0.f;
                if (bias1) bv += bias1[c];
                if (bias2) bv += bias2[c];
                C[r * ldc + c] = cr[j] + bv;
            }
        }
    }
}

// ---------------- BiLSTM recurrence (R15 champion, byte-identical math) ----------------
// + pointer-walking gx/hout indexing (IMADs off the issue stream).
__global__ void __cluster_dims__(8, 1, 1) __launch_bounds__(256, 1)
lstm_kernel(const float* __restrict__ WhhF, const float* __restrict__ WhhB,
            const float* __restrict__ gxF,  const float* __restrict__ gxB,
            float* __restrict__ hout)
{
    __shared__ __align__(16) float hbuf[2][256];          // ping-pong full h vector
    __shared__ __align__(16) float stage[2][32];          // ping-pong outgoing slice
    __shared__ __align__(8) unsigned long long mbar[2];   // ping-pong (bar[t&1])

    int tid   = threadIdx.x;
    uint32_t crank = cluster_rank_();
    int dir   = blockIdx.x >> 3;           // 0 = fwd, 1 = bwd
    const float* Whh = dir ? WhhB : WhhF;
    const float* gx  = dir ? gxB  : gxF;

    int lane = tid & 31, w = tid >> 5;
    int gate = lane >> 3;                  // 0=i 1=f 2=g 3=o
    int ul   = (lane >> 1) & 3;            // unit within warp
    int hf   = lane & 1;                   // which half of h
    int unit = w * 4 + ul;                 // unit within CTA (0..31)
    int grow = gate * 256 + (int)crank * 32 + unit;

    // register-resident weights, packed f32x2 (128 floats per lane)
    unsigned long long w2[64];
    const ulonglong2* wsrc = reinterpret_cast<const ulonglong2*>(Whh + grow * 256 + hf * 128);
#pragma unroll
    for (int k = 0; k < 32; k++) {
        ulonglong2 v = wsrc[k];
        w2[2 * k] = v.x; w2[2 * k + 1] = v.y;
    }

    for (int i = tid; i < 512; i += 256) (&hbuf[0][0])[i] = 0.f;
    if (tid == 0) {
        uint32_t b0 = smem_u32(&mbar[0]);
        asm volatile("mbarrier.init.shared.b64 [%0], 1;" :: "r"(b0) : "memory");
        asm volatile("mbarrier.init.shared.b64 [%0], 1;" :: "r"(b0 + 8) : "memory");
    }
    __syncthreads();
    cluster_sync_();   // bars initialized + h zeroed before anyone copies/arrives

    uint32_t hbase   = smem_u32(&hbuf[0][0]);
    uint32_t stbase  = smem_u32(&stage[0][0]);
    uint32_t barbase = smem_u32(&mbar[0]);

    // sender mapping (warp7, lanes 0..7: peer = lane)
    uint32_t peer  = (uint32_t)(lane & 7);
    uint32_t mych  = (uint32_t)crank * 128u;
    uint32_t dstP0 = mapa_u32(hbase + mych,          peer);  // into peer hbuf[0]
    uint32_t dstP1 = mapa_u32(hbase + 1024u + mych,  peer);  // into peer hbuf[1]
    uint32_t rb0   = mapa_u32(barbase,      peer);           // peer bar[0]
    uint32_t rb1   = mapa_u32(barbase + 8u, peer);           // peer bar[1]

    float cstate = 0.f;

    // pointer-walked gx / hout (no per-step IMAD)
    int s0 = dir ? (S_LEN - 1) : 0;
    int gstride = dir ? -G4 : G4;
    const float* gxp = gx + s0 * G4 + grow;
    float gxv = *gxp;
    int hstride = dir ? -512 : 512;
    float* houtp = hout + s0 * 512 + dir * 256 + (int)crank * 32 + unit;

    for (int t = 0; t < S_LEN; t++) {
        // arm event t: 8 peers x 128B into hbuf[(t+1)&1], counted at bar[t&1]
        if (tid == 0)
            arrive_expect_tx(barbase + ((uint32_t)t & 1u) * 8u, 1024u);

        // prefetch next step's gx BEFORE parking (LDG flies during the wait)
        float gxn = 0.f;
        if (t + 1 < S_LEN)
            gxn = gxp[gstride];

        // wait event t-1 (h(t) fully delivered into hbuf[t&1]); parked
        if (t > 0) {
            uint32_t e = (uint32_t)(t - 1);
            wait_parity(barbase + (e & 1u) * 8u, (e >> 1) & 1u);
        }

        // 128-wide dot product, packed f32x2, 4 accumulator chains
        const ulonglong2* hv = reinterpret_cast<const ulonglong2*>(&hbuf[t & 1][hf * 128]);
        unsigned long long a0 = 0ull, a1 = 0ull, a2 = 0ull, a3 = 0ull;
#pragma unroll
        for (int k = 0; k < 32; k += 2) {
            ulonglong2 hA2 = hv[k];
            ulonglong2 hB2 = hv[k + 1];
            FMA2(a0, w2[2 * k],     hA2.x);
            FMA2(a1, w2[2 * k + 1], hA2.y);
            FMA2(a2, w2[2 * k + 2], hB2.x);
            FMA2(a3, w2[2 * k + 3], hB2.y);
        }
        float f0, f1, f2, f3, f4, f5, f6, f7;
        UNPACK2(f0, f1, a0);
        UNPACK2(f2, f3, a1);
        UNPACK2(f4, f5, a2);
        UNPACK2(f6, f7, a3);
        float dot = ((f0 + f1) + (f2 + f3)) + ((f4 + f5) + (f6 + f7));
        dot += __shfl_xor_sync(0xffffffffu, dot, 1);

        // gate activation via single-MUFU tanh:
        //   g gate (gate==2): act = tanh(v)
        //   i/f/o gates:      act = 0.5 + 0.5*tanh(v/2)
        float v  = gxv + dot;
        float z  = (gate == 2) ? v : 0.5f * v;
        float th = tanh_mufu(z);
        float act = (gate == 2) ? th : fmaf(0.5f, th, 0.5f);

        // gather f, g, o to the i-gate lanes of each unit
        int srcb = lane & 7;
        float gf = __shfl_sync(0xffffffffu, act, srcb + 8);
        float gg = __shfl_sync(0xffffffffu, act, srcb + 16);
        float go = __shfl_sync(0xffffffffu, act, srcb + 24);

        cstate = fmaf(gf, cstate, act * gg);
        float hn = go * tanh_mufu(cstate);

        // stage this warp's 4 h values (same parity as target hbuf)
        if (gate == 0 && hf == 0)
            stage[(t + 1) & 1][unit] = hn;

        if (w != 7) {
            asm volatile("bar.arrive 1, 256;" ::: "memory");
        } else {
            asm volatile("bar.sync 1, 256;" ::: "memory");   // drains all warps' STS
            if (t < S_LEN - 1) {          // event S-1 (h(S)) is never consumed: skip
                fence_proxy_async_cta();  // make stage async-visible
                if (lane < 8) {
                    uint32_t src = stbase + (uint32_t)(((t + 1) & 1) * 128);
                    uint32_t d   = (t & 1) ? dstP0 : dstP1;   // write hbuf[(t+1)&1]
                    uint32_t b   = (t & 1) ? rb1   : rb0;     // account at bar[t&1]
                    bulk_copy_cluster(d, src, 128u, b);
                }
            }
        }

        // off critical path: write h to global
        if (gate == 0 && hf == 0)
            *houtp = hn;
        houtp += hstride;
        gxp   += gstride;
        gxv = gxn;
    }
    // no drain needed: the last copies (event S-2) completed before every CTA
    // passed its final wait; event S-1 was never sent.
    cluster_sync_();
}

// ---------------- pairwise scorer ----------------
__global__ __launch_bounds__(256) void scorer_kernel(
    const float* __restrict__ hA, const float* __restrict__ hB,
    const float* __restrict__ W2, const float* __restrict__ b2,
    float* __restrict__ out)
{
    __shared__ float sA[16][129];
    __shared__ float sB[16][129];
    __shared__ float sw[128];
    int tid = threadIdx.x;
    int j0 = blockIdx.x * 16, i0 = blockIdx.y * 16;

    for (int idx = tid; idx < 16 * 128; idx += 256) {
        int r = idx >> 7, k = idx & 127;
        sA[r][k] = hA[(i0 + r) * MLPD + k];
        sB[r][k] = hB[(j0 + r) * MLPD + k];
    }
    if (tid < 128) sw[tid] = W2[tid];
    __syncthreads();

    int tx = tid & 15, ty = tid >> 4;
    float acc = b2[0];
#pragma unroll 4
    for (int k = 0; k < 128; k++) {
        float v = sA[ty][k] + sB[tx][k];
        acc = fmaf(sw[k], tanh_mufu(v), acc);
    }
    int i = i0 + ty, j = j0 + tx;
    out[i * S_LEN + j] = (i == j) ? 0.f : acc;
}

// ---------------- launch ----------------
extern "C" void kernel_launch(void* const* d_in, const int* in_sizes, int n_in,
                              void* d_out, int out_size)
{
    int base = (in_sizes[2] < 1000) ? 3 : 2;

    const int* widx = (const int*)d_in[0];
    const int* pidx = (const int*)d_in[1];
    const float* W_word = (const float*)d_in[base + 0];
    const float* W_pos  = (const float*)d_in[base + 1];
    const float *Wih[4], *Whh[4], *bih[4], *bhh[4];
    for (int i = 0; i < 4; i++) {
        Wih[i] = (const float*)d_in[base + 2 + 4 * i];
        Whh[i] = (const float*)d_in[base + 3 + 4 * i];
        bih[i] = (const float*)d_in[base + 4 + 4 * i];
        bhh[i] = (const float*)d_in[base + 5 + 4 * i];
    }
    const float* W1 = (const float*)d_in[base + 18];
    const float* b1 = (const float*)d_in[base + 19];
    const float* W2 = (const float*)d_in[base + 20];
    const float* b2 = (const float*)d_in[base + 21];
    float* out = (float*)d_out;

    float *xp, *gxF, *gxB, *h0, *h1, *hA, *hB;
    cudaGetSymbolAddress((void**)&xp,  d_x);
    cudaGetSymbolAddress((void**)&gxF, d_gxF);
    cudaGetSymbolAddress((void**)&gxB, d_gxB);
    cudaGetSymbolAddress((void**)&h0,  d_h0);
    cudaGetSymbolAddress((void**)&h1,  d_h1);
    cudaGetSymbolAddress((void**)&hA,  d_hA);
    cudaGetSymbolAddress((void**)&hB,  d_hB);

    // 1) embeddings
    embed_kernel<<<S_LEN, EMB>>>(widx, pidx, W_word, W_pos);

    // 2) layer-0 input GEMMs (fwd + bwd in ONE launch): gx = x @ Wih^T + biases
    dim3 gGX(G4 / 64, S_LEN / 64, 2);
    gemm_pair_kernel<<<gGX, 256>>>(xp, EMB,
                                   Wih[0], Wih[1], EMB,
                                   bih[0], bih[1], bhh[0], bhh[1],
                                   gxF, gxB, G4, S_LEN, G4, EMB);

    // 3) layer-0 recurrence (fwd + bwd concurrently)
    lstm_kernel<<<16, 256>>>(Whh[0], Whh[1], gxF, gxB, h0);

    // 4) layer-1 input GEMMs (pair, K = 512)
    gemm_pair_kernel<<<gGX, 256>>>(h0, 512,
                                   Wih[2], Wih[3], 512,
                                   bih[2], bih[3], bhh[2], bhh[3],
                                   gxF, gxB, G4, S_LEN, G4, 512);

    // 5) layer-1 recurrence
    lstm_kernel<<<16, 256>>>(Whh[2], Whh[3], gxF, gxB, h1);

    // 6) scorer projections (pair): hA = h1 @ W1[:, :512]^T + b1 ; hB = h1 @ W1[:, 512:]^T
    dim3 gAB(MLPD / 64, S_LEN / 64, 2);
    gemm_pair_kernel<<<gAB, 256>>>(h1, 512,
                                   W1, W1 + 512, 1024,
                                   b1, nullptr, nullptr, nullptr,
                                   hA, hB, MLPD, S_LEN, MLPD, 512);

    // 7) pairwise scores [768,768], diag = 0
    scorer_kernel<<<dim3(S_LEN / 16, S_LEN / 16), 256>>>(hA, hB, W2, b2, out);
}

// round 17
// speedup vs baseline: 1.3725x; 1.0000x over previous
#include <cuda_runtime.h>
#include <cstdint>
#include <math.h>

#define S_LEN 768
#define EMB   128
#define HDIM  256
#define G4    1024
#define MLPD  128

// ---------------- scratch (static device memory; no allocation) ----------------
__device__ float d_x  [S_LEN * EMB];
__device__ float d_gxF[S_LEN * G4];
__device__ float d_gxB[S_LEN * G4];
__device__ float d_h0 [S_LEN * 2 * HDIM];
__device__ float d_h1 [S_LEN * 2 * HDIM];
__device__ float d_hA [S_LEN * MLPD];
__device__ float d_hB [S_LEN * MLPD];

// ---------------- fast activations ----------------
__device__ __forceinline__ float tanh_mufu(float x) {
    float r; asm("tanh.approx.f32 %0, %1;" : "=f"(r) : "f"(x)); return r;
}

// ---------------- cluster / mbarrier helpers ----------------
__device__ __forceinline__ uint32_t smem_u32(const void* p) {
    uint32_t a;
    asm("{ .reg .u64 t; cvta.to.shared.u64 t, %1; cvt.u32.u64 %0, t; }"
        : "=r"(a) : "l"(p));
    return a;
}
__device__ __forceinline__ uint32_t mapa_u32(uint32_t local_addr, uint32_t rank) {
    uint32_t rem;
    asm volatile("mapa.shared::cluster.u32 %0, %1, %2;"
                 : "=r"(rem) : "r"(local_addr), "r"(rank));
    return rem;
}
__device__ __forceinline__ void bulk_copy_cluster(uint32_t dst_cluster, uint32_t src_cta,
                                                  uint32_t bytes, uint32_t bar_cluster) {
    asm volatile(
        "cp.async.bulk.shared::cluster.shared::cta.mbarrier::complete_tx::bytes "
        "[%0], [%1], %2, [%3];"
        :: "r"(dst_cluster), "r"(src_cta), "r"(bytes), "r"(bar_cluster) : "memory");
}
__device__ __forceinline__ void fence_proxy_async_cta() {
    asm volatile("fence.proxy.async.shared::cta;" ::: "memory");
}
__device__ __forceinline__ void arrive_expect_tx(uint32_t bar, uint32_t bytes) {
    asm volatile("mbarrier.arrive.expect_tx.shared.b64 _, [%0], %1;"
                 :: "r"(bar), "r"(bytes) : "memory");
}
__device__ __forceinline__ void wait_parity(uint32_t bar, uint32_t parity) {
    uint32_t done;
    asm volatile(
        "{\n\t"
        ".reg .pred P;\n\t"
        "mbarrier.try_wait.parity.acquire.cta.shared::cta.b64 P, [%1], %2;\n\t"
        "selp.b32 %0, 1, 0, P;\n\t"
        "}"
        : "=r"(done) : "r"(bar), "r"(parity) : "memory");
    if (!done) {
        asm volatile(
            "{\n\t"
            ".reg .pred P;\n\t"
            "W%=:\n\t"
            "mbarrier.try_wait.parity.acquire.cta.shared::cta.b64 P, [%0], %1, 0x989680;\n\t"
            "@!P bra W%=;\n\t"
            "}"
            :: "r"(bar), "r"(parity) : "memory");
    }
}
__device__ __forceinline__ void cluster_sync_() {
    asm volatile("barrier.cluster.arrive.aligned;" ::: "memory");
    asm volatile("barrier.cluster.wait.aligned;" ::: "memory");
}
__device__ __forceinline__ uint32_t cluster_rank_() {
    uint32_t r; asm("mov.u32 %0, %%cluster_ctarank;" : "=r"(r)); return r;
}

#define FMA2(acc, w, h) \
    asm("fma.rn.f32x2 %0, %1, %2, %0;" : "+l"(acc) : "l"(w), "l"(h))
#define PACK2(out, lo, hi) \
    asm("mov.b64 %0, {%1, %2};" : "=l"(out) : "f"(lo), "f"(hi))
#define UNPACK2(lo, hi, in) \
    asm("mov.b64 {%0, %1}, %2;" : "=f"(lo), "=f"(hi) : "l"(in))

// ---------------- embedding gather ----------------
__global__ void embed_kernel(const int* __restrict__ widx, const int* __restrict__ pidx,
                             const float* __restrict__ Ww, const float* __restrict__ Wp) {
    int s = blockIdx.x, f = threadIdx.x;
    float v = (f < 100) ? Ww[widx[s] * 100 + f] : Wp[pidx[s] * 28 + (f - 100)];
    d_x[s * EMB + f] = v;
}

// ---------------- batched pair GEMM (exact shapes, double-buffered) ----------------
// C[M,N] = A[M,K] * B[N,K]^T + bias1 + bias2 for z in {0,1}.
// Requirements (all callers satisfy): M,N multiples of 64; K multiple of 16.
// Inner loop = packed f32x2 (scalar FFMA is half-rate on sm_103a); B fragment
// loaded directly as ulonglong from smem (no repack); 2-deep smem ping-pong
// overlaps next tile's LDG with current tile's FMA2 at ONE syncthreads/tile.
__global__ __launch_bounds__(256) void gemm_pair_kernel(
    const float* __restrict__ A, int lda,
    const float* __restrict__ B0, const float* __restrict__ B1, int ldb,
    const float* __restrict__ b1a, const float* __restrict__ b1b,
    const float* __restrict__ b2a, const float* __restrict__ b2b,
    float* __restrict__ C0, float* __restrict__ C1, int ldc,
    int M, int N, int K)
{
    int z = blockIdx.z;
    const float* B     = z ? B1  : B0;
    const float* bias1 = z ? b1b : b1a;
    const float* bias2 = z ? b2b : b2a;
    float* C           = z ? C1  : C0;

    __shared__ __align__(16) float As[2][16][68];
    __shared__ __align__(16) float Bs[2][16][68];
    int tid = threadIdx.x;
    int bx = blockIdx.x, by = blockIdx.y;
    int tx = tid & 15, ty = tid >> 4;
    int m0 = by * 64 + ty * 4;
    int n0 = bx * 64 + tx * 4;

    // per-thread load coordinates (4 elements per buffer fill)
    int lr  = tid >> 4;          // row within 64-row tile (0..15 per chunk)
    int lkk = tid & 15;          // k within 16-wide tile
    const float* Ab = A + (by * 64) * lda + lkk;
    const float* Bb = B + (bx * 64) * ldb + lkk;

    unsigned long long acc2[4][2];
#pragma unroll
    for (int i = 0; i < 4; i++) { acc2[i][0] = 0ull; acc2[i][1] = 0ull; }

    int KT = K >> 4;

    // preload tile 0
#pragma unroll
    for (int i = 0; i < 4; i++) {
        int r = lr + i * 16;
        As[0][lkk][r] = Ab[r * lda];
        Bs[0][lkk][r] = Bb[r * ldb];
    }
    __syncthreads();

    for (int kt = 0; kt < KT; kt++) {
        int cur = kt & 1;
        // prefetch next tile into the other buffer (overlaps with FMA below)
        if (kt + 1 < KT) {
            const float* An = Ab + (kt + 1) * 16;
            const float* Bn = Bb + (kt + 1) * 16;
#pragma unroll
            for (int i = 0; i < 4; i++) {
                int r = lr + i * 16;
                As[cur ^ 1][lkk][r] = An[r * lda];
                Bs[cur ^ 1][lkk][r] = Bn[r * ldb];
            }
        }
#pragma unroll
        for (int kk = 0; kk < 16; kk++) {
            float4 av = *reinterpret_cast<const float4*>(&As[cur][kk][ty * 4]);
            const unsigned long long* bp =
                reinterpret_cast<const unsigned long long*>(&Bs[cur][kk][tx * 4]);
            unsigned long long b01 = bp[0], b23 = bp[1];
            float a[4] = {av.x, av.y, av.z, av.w};
#pragma unroll
            for (int i = 0; i < 4; i++) {
                unsigned long long a2;
                PACK2(a2, a[i], a[i]);
                FMA2(acc2[i][0], a2, b01);
                FMA2(acc2[i][1], a2, b23);
            }
        }
        __syncthreads();   // next-tile stores done AND current-buffer reads done
    }

#pragma unroll
    for (int i = 0; i < 4; i++) {
        float c0, c1, c2, c3;
        UNPACK2(c0, c1, acc2[i][0]);
        UNPACK2(c2, c3, acc2[i][1]);
        float cr[4] = {c0, c1, c2, c3};
        int r = m0 + i;
#pragma unroll
        for (int j = 0; j < 4; j++) {
            int c = n0 + j;
            float bv = 0.f;
            if (bias1) bv += bias1[c];
            if (bias2) bv += bias2[c];
            C[r * ldc + c] = cr[j] + bv;
        }
    }
}

// ---------------- BiLSTM recurrence (R15/R16 champion, byte-identical) ----------------
__global__ void __cluster_dims__(8, 1, 1) __launch_bounds__(256, 1)
lstm_kernel(const float* __restrict__ WhhF, const float* __restrict__ WhhB,
            const float* __restrict__ gxF,  const float* __restrict__ gxB,
            float* __restrict__ hout)
{
    __shared__ __align__(16) float hbuf[2][256];          // ping-pong full h vector
    __shared__ __align__(16) float stage[2][32];          // ping-pong outgoing slice
    __shared__ __align__(8) unsigned long long mbar[2];   // ping-pong (bar[t&1])

    int tid   = threadIdx.x;
    uint32_t crank = cluster_rank_();
    int dir   = blockIdx.x >> 3;           // 0 = fwd, 1 = bwd
    const float* Whh = dir ? WhhB : WhhF;
    const float* gx  = dir ? gxB  : gxF;

    int lane = tid & 31, w = tid >> 5;
    int gate = lane >> 3;                  // 0=i 1=f 2=g 3=o
    int ul   = (lane >> 1) & 3;            // unit within warp
    int hf   = lane & 1;                   // which half of h
    int unit = w * 4 + ul;                 // unit within CTA (0..31)
    int grow = gate * 256 + (int)crank * 32 + unit;

    // register-resident weights, packed f32x2 (128 floats per lane)
    unsigned long long w2[64];
    const ulonglong2* wsrc = reinterpret_cast<const ulonglong2*>(Whh + grow * 256 + hf * 128);
#pragma unroll
    for (int k = 0; k < 32; k++) {
        ulonglong2 v = wsrc[k];
        w2[2 * k] = v.x; w2[2 * k + 1] = v.y;
    }

    for (int i = tid; i < 512; i += 256) (&hbuf[0][0])[i] = 0.f;
    if (tid == 0) {
        uint32_t b0 = smem_u32(&mbar[0]);
        asm volatile("mbarrier.init.shared.b64 [%0], 1;" :: "r"(b0) : "memory");
        asm volatile("mbarrier.init.shared.b64 [%0], 1;" :: "r"(b0 + 8) : "memory");
    }
    __syncthreads();
    cluster_sync_();   // bars initialized + h zeroed before anyone copies/arrives

    uint32_t hbase   = smem_u32(&hbuf[0][0]);
    uint32_t stbase  = smem_u32(&stage[0][0]);
    uint32_t barbase = smem_u32(&mbar[0]);

    // sender mapping (warp7, lanes 0..7: peer = lane)
    uint32_t peer  = (uint32_t)(lane & 7);
    uint32_t mych  = (uint32_t)crank * 128u;
    uint32_t dstP0 = mapa_u32(hbase + mych,          peer);  // into peer hbuf[0]
    uint32_t dstP1 = mapa_u32(hbase + 1024u + mych,  peer);  // into peer hbuf[1]
    uint32_t rb0   = mapa_u32(barbase,      peer);           // peer bar[0]
    uint32_t rb1   = mapa_u32(barbase + 8u, peer);           // peer bar[1]

    float cstate = 0.f;

    // pointer-walked gx / hout (no per-step IMAD)
    int s0 = dir ? (S_LEN - 1) : 0;
    int gstride = dir ? -G4 : G4;
    const float* gxp = gx + s0 * G4 + grow;
    float gxv = *gxp;
    int hstride = dir ? -512 : 512;
    float* houtp = hout + s0 * 512 + dir * 256 + (int)crank * 32 + unit;

    for (int t = 0; t < S_LEN; t++) {
        // arm event t: 8 peers x 128B into hbuf[(t+1)&1], counted at bar[t&1]
        if (tid == 0)
            arrive_expect_tx(barbase + ((uint32_t)t & 1u) * 8u, 1024u);

        // prefetch next step's gx BEFORE parking (LDG flies during the wait)
        float gxn = 0.f;
        if (t + 1 < S_LEN)
            gxn = gxp[gstride];

        // wait event t-1 (h(t) fully delivered into hbuf[t&1]); parked
        if (t > 0) {
            uint32_t e = (uint32_t)(t - 1);
            wait_parity(barbase + (e & 1u) * 8u, (e >> 1) & 1u);
        }

        // 128-wide dot product, packed f32x2, 4 accumulator chains
        const ulonglong2* hv = reinterpret_cast<const ulonglong2*>(&hbuf[t & 1][hf * 128]);
        unsigned long long a0 = 0ull, a1 = 0ull, a2 = 0ull, a3 = 0ull;
#pragma unroll
        for (int k = 0; k < 32; k += 2) {
            ulonglong2 hA2 = hv[k];
            ulonglong2 hB2 = hv[k + 1];
            FMA2(a0, w2[2 * k],     hA2.x);
            FMA2(a1, w2[2 * k + 1], hA2.y);
            FMA2(a2, w2[2 * k + 2], hB2.x);
            FMA2(a3, w2[2 * k + 3], hB2.y);
        }
        float f0, f1, f2, f3, f4, f5, f6, f7;
        UNPACK2(f0, f1, a0);
        UNPACK2(f2, f3, a1);
        UNPACK2(f4, f5, a2);
        UNPACK2(f6, f7, a3);
        float dot = ((f0 + f1) + (f2 + f3)) + ((f4 + f5) + (f6 + f7));
        dot += __shfl_xor_sync(0xffffffffu, dot, 1);

        // gate activation via single-MUFU tanh:
        //   g gate (gate==2): act = tanh(v)
        //   i/f/o gates:      act = 0.5 + 0.5*tanh(v/2)
        float v  = gxv + dot;
        float z  = (gate == 2) ? v : 0.5f * v;
        float th = tanh_mufu(z);
        float act = (gate == 2) ? th : fmaf(0.5f, th, 0.5f);

        // gather f, g, o to the i-gate lanes of each unit
        int srcb = lane & 7;
        float gf = __shfl_sync(0xffffffffu, act, srcb + 8);
        float gg = __shfl_sync(0xffffffffu, act, srcb + 16);
        float go = __shfl_sync(0xffffffffu, act, srcb + 24);

        cstate = fmaf(gf, cstate, act * gg);
        float hn = go * tanh_mufu(cstate);

        // stage this warp's 4 h values (same parity as target hbuf)
        if (gate == 0 && hf == 0)
            stage[(t + 1) & 1][unit] = hn;

        if (w != 7) {
            asm volatile("bar.arrive 1, 256;" ::: "memory");
        } else {
            asm volatile("bar.sync 1, 256;" ::: "memory");   // drains all warps' STS
            if (t < S_LEN - 1) {          // event S-1 (h(S)) is never consumed: skip
                fence_proxy_async_cta();  // make stage async-visible
                if (lane < 8) {
                    uint32_t src = stbase + (uint32_t)(((t + 1) & 1) * 128);
                    uint32_t d   = (t & 1) ? dstP0 : dstP1;   // write hbuf[(t+1)&1]
                    uint32_t b   = (t & 1) ? rb1   : rb0;     // account at bar[t&1]
                    bulk_copy_cluster(d, src, 128u, b);
                }
            }
        }

        // off critical path: write h to global
        if (gate == 0 && hf == 0)
            *houtp = hn;
        houtp += hstride;
        gxp   += gstride;
        gxv = gxn;
    }
    // no drain needed: the last copies (event S-2) completed before every CTA
    // passed its final wait; event S-1 was never sent.
    cluster_sync_();
}

// ---------------- pairwise scorer ----------------
__global__ __launch_bounds__(256) void scorer_kernel(
    const float* __restrict__ hA, const float* __restrict__ hB,
    const float* __restrict__ W2, const float* __restrict__ b2,
    float* __restrict__ out)
{
    __shared__ float sA[16][129];
    __shared__ float sB[16][129];
    __shared__ float sw[128];
    int tid = threadIdx.x;
    int j0 = blockIdx.x * 16, i0 = blockIdx.y * 16;

    for (int idx = tid; idx < 16 * 128; idx += 256) {
        int r = idx >> 7, k = idx & 127;
        sA[r][k] = hA[(i0 + r) * MLPD + k];
        sB[r][k] = hB[(j0 + r) * MLPD + k];
    }
    if (tid < 128) sw[tid] = W2[tid];
    __syncthreads();

    int tx = tid & 15, ty = tid >> 4;
    float acc = b2[0];
#pragma unroll 4
    for (int k = 0; k < 128; k++) {
        float v = sA[ty][k] + sB[tx][k];
        acc = fmaf(sw[k], tanh_mufu(v), acc);
    }
    int i = i0 + ty, j = j0 + tx;
    out[i * S_LEN + j] = (i == j) ? 0.f : acc;
}

// ---------------- launch ----------------
extern "C" void kernel_launch(void* const* d_in, const int* in_sizes, int n_in,
                              void* d_out, int out_size)
{
    int base = (in_sizes[2] < 1000) ? 3 : 2;

    const int* widx = (const int*)d_in[0];
    const int* pidx = (const int*)d_in[1];
    const float* W_word = (const float*)d_in[base + 0];
    const float* W_pos  = (const float*)d_in[base + 1];
    const float *Wih[4], *Whh[4], *bih[4], *bhh[4];
    for (int i = 0; i < 4; i++) {
        Wih[i] = (const float*)d_in[base + 2 + 4 * i];
        Whh[i] = (const float*)d_in[base + 3 + 4 * i];
        bih[i] = (const float*)d_in[base + 4 + 4 * i];
        bhh[i] = (const float*)d_in[base + 5 + 4 * i];
    }
    const float* W1 = (const float*)d_in[base + 18];
    const float* b1 = (const float*)d_in[base + 19];
    const float* W2 = (const float*)d_in[base + 20];
    const float* b2 = (const float*)d_in[base + 21];
    float* out = (float*)d_out;

    float *xp, *gxF, *gxB, *h0, *h1, *hA, *hB;
    cudaGetSymbolAddress((void**)&xp,  d_x);
    cudaGetSymbolAddress((void**)&gxF, d_gxF);
    cudaGetSymbolAddress((void**)&gxB, d_gxB);
    cudaGetSymbolAddress((void**)&h0,  d_h0);
    cudaGetSymbolAddress((void**)&h1,  d_h1);
    cudaGetSymbolAddress((void**)&hA,  d_hA);
    cudaGetSymbolAddress((void**)&hB,  d_hB);

    // 1) embeddings
    embed_kernel<<<S_LEN, EMB>>>(widx, pidx, W_word, W_pos);

    // 2) layer-0 input GEMMs (fwd + bwd in ONE launch): gx = x @ Wih^T + biases
    dim3 gGX(G4 / 64, S_LEN / 64, 2);
    gemm_pair_kernel<<<gGX, 256>>>(xp, EMB,
                                   Wih[0], Wih[1], EMB,
                                   bih[0], bih[1], bhh[0], bhh[1],
                                   gxF, gxB, G4, S_LEN, G4, EMB);

    // 3) layer-0 recurrence (fwd + bwd concurrently)
    lstm_kernel<<<16, 256>>>(Whh[0], Whh[1], gxF, gxB, h0);

    // 4) layer-1 input GEMMs (pair, K = 512)
    gemm_pair_kernel<<<gGX, 256>>>(h0, 512,
                                   Wih[2], Wih[3], 512,
                                   bih[2], bih[3], bhh[2], bhh[3],
                                   gxF, gxB, G4, S_LEN, G4, 512);

    // 5) layer-1 recurrence
    lstm_kernel<<<16, 256>>>(Whh[2], Whh[3], gxF, gxB, h1);

    // 6) scorer projections (pair): hA = h1 @ W1[:, :512]^T + b1 ; hB = h1 @ W1[:, 512:]^T
    dim3 gAB(MLPD / 64, S_LEN / 64, 2);
    gemm_pair_kernel<<<gAB, 256>>>(h1, 512,
                                   W1, W1 + 512, 1024,
                                   b1, nullptr, nullptr, nullptr,
                                   hA, hB, MLPD, S_LEN, MLPD, 512);

    // 7) pairwise scores [768,768], diag = 0
    scorer_kernel<<<dim3(S_LEN / 16, S_LEN / 16), 256>>>(hA, hB, W2, b2, out);
}